// round 3
// baseline (speedup 1.0000x reference)
#include <cuda_runtime.h>

// ---------------- problem constants ----------------
#define D     128
#define BM    128
#define BN    128
#define BK    16
#define TM    8
#define TN    8
#define NSPLIT 7
#define MAXN  8192

// ---------------- device scratch (no allocs allowed) ----------------
__device__ float g_en[MAXN * D];                  // normalized embeddings, 4MB
__device__ unsigned long long g_pos[MAXN];        // packed (keyed dot, idx)
__device__ unsigned long long g_neg[MAXN];

// order-preserving float -> uint key (monotonic increasing)
__device__ __forceinline__ unsigned int f2k(float f) {
    unsigned int u = __float_as_uint(f);
    return (u & 0x80000000u) ? ~u : (u | 0x80000000u);
}
__device__ __forceinline__ float k2f(unsigned int k) {
    unsigned int u = (k & 0x80000000u) ? (k ^ 0x80000000u) : ~k;
    return __uint_as_float(u);
}

// ---------------- kernel 1: reset merge keys ----------------
__global__ void init_keys_k(int n) {
    int i = blockIdx.x * blockDim.x + threadIdx.x;
    if (i < n) {
        g_pos[i] = ~0ull;  // any real (min) key is smaller
        g_neg[i] = 0ull;   // any real (max) key is larger
    }
}

// ---------------- kernel 2: L2-normalize rows ----------------
__global__ void normalize_k(const float* __restrict__ E) {
    int row = blockIdx.x;
    int t = threadIdx.x;          // 0..127 == d index
    float v = E[row * D + t];
    float ss = v * v;
    #pragma unroll
    for (int o = 16; o > 0; o >>= 1) ss += __shfl_xor_sync(0xFFFFFFFFu, ss, o);
    __shared__ float w[4];
    if ((t & 31) == 0) w[t >> 5] = ss;
    __syncthreads();
    float tot = w[0] + w[1] + w[2] + w[3];
    float m = fmaxf(sqrtf(tot), 1e-8f);            // matches max(norm, eps)
    g_en[row * D + t] = v / m;
}

// ---------------- kernel 3: fused GEMM + masked hardest-pos/neg ----------------
// NOTE: labels is INT32 on the wire (JAX default config downgrades int64->int32).
__global__ __launch_bounds__(256)
void miner_k(const int* __restrict__ labels, int n) {
    const int mi    = blockIdx.x;       // anchor tile
    const int split = blockIdx.y;       // j-range split
    const int ntiles = n / BN;
    const int jt0 = (split * ntiles) / NSPLIT;
    const int jt1 = ((split + 1) * ntiles) / NSPLIT;

    const int tid = threadIdx.x;        // 0..255
    const int tx = tid & 15;
    const int ty = tid >> 4;
    const int row0 = mi * BM + ty * TM; // first of my TM anchor rows

    __shared__ float As[BK][BM];
    __shared__ float Bs[BK][BN];
    __shared__ int sLab[BN];
    __shared__ unsigned long long sPos[BM];
    __shared__ unsigned long long sNeg[BM];

    // running candidates in "dot" space:
    //   hardest positive  = MIN dot over same-label (j != i)  -> max distance
    //   hardest negative  = MAX dot over diff-label           -> min distance
    float posDot[TM], negDot[TM];
    int   posIdx[TM], negIdx[TM];
    int   myLab[TM];
    #pragma unroll
    for (int tm = 0; tm < TM; ++tm) {
        posDot[tm] = __int_as_float(0x7F800000);   // +inf
        negDot[tm] = __int_as_float(0xFF800000);   // -inf
        posIdx[tm] = 0; negIdx[tm] = 0;
        myLab[tm] = labels[row0 + tm];
    }

    const float* __restrict__ EN = g_en;
    // per-thread source coordinates for the A/B tile loads
    const int aR  = tid >> 2;               // rows 0..63
    const int aC4 = (tid & 3) << 2;         // col4 offset within BK chunk
    const int bR  = aR + 64;                // rows 64..127
    const float* aSrc0 = &EN[(size_t)(mi * BM + aR) * D + aC4];
    const float* aSrc1 = &EN[(size_t)(mi * BM + bR) * D + aC4];

    for (int jt = jt0; jt < jt1; ++jt) {
        const int j0 = jt * BN;
        __syncthreads();   // protect sLab/smem against prior-iteration readers
        if (tid < BN) sLab[tid] = labels[j0 + tid];

        float acc[TM][TN];
        #pragma unroll
        for (int a = 0; a < TM; ++a)
            #pragma unroll
            for (int b = 0; b < TN; ++b) acc[a][b] = 0.0f;

        const float* bSrc0 = &EN[(size_t)(j0 + aR) * D + aC4];
        const float* bSrc1 = &EN[(size_t)(j0 + bR) * D + aC4];

        #pragma unroll
        for (int k0 = 0; k0 < D; k0 += BK) {
            // load A tile (BM x BK), store transposed As[k][m]
            {
                float4 v = *reinterpret_cast<const float4*>(aSrc0 + k0);
                As[aC4 + 0][aR] = v.x; As[aC4 + 1][aR] = v.y;
                As[aC4 + 2][aR] = v.z; As[aC4 + 3][aR] = v.w;
                float4 w4 = *reinterpret_cast<const float4*>(aSrc1 + k0);
                As[aC4 + 0][bR] = w4.x; As[aC4 + 1][bR] = w4.y;
                As[aC4 + 2][bR] = w4.z; As[aC4 + 3][bR] = w4.w;
            }
            // load B tile (BN x BK), store transposed Bs[k][j]
            {
                float4 v = *reinterpret_cast<const float4*>(bSrc0 + k0);
                Bs[aC4 + 0][aR] = v.x; Bs[aC4 + 1][aR] = v.y;
                Bs[aC4 + 2][aR] = v.z; Bs[aC4 + 3][aR] = v.w;
                float4 w4 = *reinterpret_cast<const float4*>(bSrc1 + k0);
                Bs[aC4 + 0][bR] = w4.x; Bs[aC4 + 1][bR] = w4.y;
                Bs[aC4 + 2][bR] = w4.z; Bs[aC4 + 3][bR] = w4.w;
            }
            __syncthreads();

            #pragma unroll
            for (int k = 0; k < BK; ++k) {
                float4 a0 = *reinterpret_cast<const float4*>(&As[k][ty * TM]);
                float4 a1 = *reinterpret_cast<const float4*>(&As[k][ty * TM + 4]);
                float4 b0 = *reinterpret_cast<const float4*>(&Bs[k][tx * TN]);
                float4 b1 = *reinterpret_cast<const float4*>(&Bs[k][tx * TN + 4]);
                float av[TM] = {a0.x, a0.y, a0.z, a0.w, a1.x, a1.y, a1.z, a1.w};
                float bv[TN] = {b0.x, b0.y, b0.z, b0.w, b1.x, b1.y, b1.z, b1.w};
                #pragma unroll
                for (int tm = 0; tm < TM; ++tm)
                    #pragma unroll
                    for (int tn = 0; tn < TN; ++tn)
                        acc[tm][tn] = fmaf(av[tm], bv[tn], acc[tm][tn]);
            }
            __syncthreads();
        }

        // masked epilogue: each dot visited once; strict compares keep FIRST index
        #pragma unroll
        for (int tn = 0; tn < TN; ++tn) {
            const int jl = tx * TN + tn;
            const int j  = j0 + jl;
            const int lj = sLab[jl];
            #pragma unroll
            for (int tm = 0; tm < TM; ++tm) {
                const float dot = acc[tm][tn];
                if (lj == myLab[tm]) {
                    if (j != row0 + tm && dot < posDot[tm]) {
                        posDot[tm] = dot; posIdx[tm] = j;
                    }
                } else {
                    if (dot > negDot[tm]) {
                        negDot[tm] = dot; negIdx[tm] = j;
                    }
                }
            }
        }
    }

    // ---- block reduce via packed keys, then global merge ----
    // pos: want MIN dot, ties -> smaller idx  => atomicMin on (key<<32 | idx)
    // neg: want MAX dot, ties -> smaller idx  => atomicMax on (key<<32 | ~idx)
    if (tid < BM) { sPos[tid] = ~0ull; sNeg[tid] = 0ull; }
    __syncthreads();
    #pragma unroll
    for (int tm = 0; tm < TM; ++tm) {
        int r = ty * TM + tm;
        unsigned long long pk =
            ((unsigned long long)f2k(posDot[tm]) << 32) | (unsigned int)posIdx[tm];
        unsigned long long nk =
            ((unsigned long long)f2k(negDot[tm]) << 32) | (unsigned int)(~(unsigned int)negIdx[tm]);
        atomicMin(&sPos[r], pk);
        atomicMax(&sNeg[r], nk);
    }
    __syncthreads();
    if (tid < BM) {
        atomicMin(&g_pos[mi * BM + tid], sPos[tid]);
        atomicMax(&g_neg[mi * BM + tid], sNeg[tid]);
    }
}

// ---------------- kernel 4: decode + write outputs ----------------
// layout: out[0 : 3n)  = triplets row-major (anchor, pos_idx, neg_idx) as float
//         out[3n : 4n) = hardest_pos_dist = 1 - minPosDot
//         out[4n : 5n) = hardest_neg_dist = 1 - maxNegDot
__global__ void finalize_k(float* __restrict__ out, int n) {
    int i = blockIdx.x * blockDim.x + threadIdx.x;
    if (i >= n) return;
    unsigned long long pk = g_pos[i];
    unsigned long long nk = g_neg[i];
    float pd = 1.0f - k2f((unsigned int)(pk >> 32));
    float nd = 1.0f - k2f((unsigned int)(nk >> 32));
    int pi = (int)(unsigned int)pk;
    int ni = (int)(~(unsigned int)nk);
    out[3 * i + 0] = (float)i;
    out[3 * i + 1] = (float)pi;
    out[3 * i + 2] = (float)ni;
    out[3 * n + i] = pd;
    out[4 * n + i] = nd;
}

// ---------------- launch ----------------
extern "C" void kernel_launch(void* const* d_in, const int* in_sizes, int n_in,
                              void* d_out, int out_size) {
    const float* E      = (const float*)d_in[0];
    const int*   labels = (const int*)d_in[1];   // int32 (JAX x64 disabled)
    const int n = in_sizes[0] / D;   // 8192

    init_keys_k<<<(n + 255) / 256, 256>>>(n);
    normalize_k<<<n, D>>>(E);
    dim3 grid(n / BM, NSPLIT);
    miner_k<<<grid, 256>>>(labels, n);
    finalize_k<<<(n + 255) / 256, 256>>>((float*)d_out, n);
}